// round 12
// baseline (speedup 1.0000x reference)
#include <cuda_runtime.h>
#include <cuda_bf16.h>
#include <cstdint>
#include <math.h>

#define KDIM 3072
#define NBC  4096
#define NMID 1024

// ---- stage geometry (bytes) ----
#define A_PITCH 80            // 32 bf16 = 64B data + 16B pad (ldsm conflict-free)
#define AHI_OFF 0
#define ALO_OFF 10240
#define BHI_OFF 20480
#define B_PITCH 544           // 128 words + 8 pad words (LDS conflict-free)
#define BLO_OFF 29184
#define STAGE_B 37888
#define SMEMB   75776         // 2 stages

// ---- scratch (no allocation allowed) ----
__device__ uint16_t g_Ahi[(size_t)3072 * 3072];
__device__ uint16_t g_Alo[(size_t)3072 * 3072];
__device__ uint32_t g_Xhi[(size_t)1536 * 4096];   // pair-packed {k even, k odd}
__device__ uint32_t g_Xlo[(size_t)1536 * 4096];
__device__ float    g_H1 [(size_t)3072 * 4096];
__device__ uint32_t g_H1hi[(size_t)1536 * 4096];
__device__ uint32_t g_H1lo[(size_t)1536 * 4096];

__device__ __forceinline__ uint32_t s2u(const void* p) {
    uint32_t a;
    asm("{\n.reg .u64 t;\ncvta.to.shared.u64 t,%1;\ncvt.u32.u64 %0,t;\n}" : "=r"(a) : "l"(p));
    return a;
}
__device__ __forceinline__ void ldsm4(uint32_t* r, uint32_t addr) {
    asm volatile("ldmatrix.sync.aligned.m8n8.x4.shared.b16 {%0,%1,%2,%3},[%4];"
                 : "=r"(r[0]), "=r"(r[1]), "=r"(r[2]), "=r"(r[3]) : "r"(addr));
}
__device__ __forceinline__ void mma16(float* d, const uint32_t* a, const uint32_t* b) {
    asm volatile("mma.sync.aligned.m16n8k16.row.col.f32.bf16.bf16.f32 "
                 "{%0,%1,%2,%3},{%4,%5,%6,%7},{%8,%9},{%0,%1,%2,%3};"
                 : "+f"(d[0]), "+f"(d[1]), "+f"(d[2]), "+f"(d[3])
                 : "r"(a[0]), "r"(a[1]), "r"(a[2]), "r"(a[3]), "r"(b[0]), "r"(b[1]));
}
__device__ __forceinline__ void cpasync16(uint32_t dst, const void* src) {
    asm volatile("cp.async.cg.shared.global [%0],[%1],16;" :: "r"(dst), "l"(src));
}
// hi = truncated bf16 bits (low16 of word = even elem), lo = rn-bf16 of residual
__device__ __forceinline__ void split2(float x0, float x1, uint32_t& hi, uint32_t& lo) {
    uint32_t b0 = __float_as_uint(x0), b1 = __float_as_uint(x1);
    hi = (b0 >> 16) | (b1 & 0xFFFF0000u);
    float l0 = x0 - __uint_as_float(b0 & 0xFFFF0000u);
    float l1 = x1 - __uint_as_float(b1 & 0xFFFF0000u);
    __nv_bfloat162 p = __floats2bfloat162_rn(l0, l1);   // .x in low half
    lo = *reinterpret_cast<uint32_t*>(&p);
}

// ---------------- pre-pass: plain hi/lo split (A matrix) --------------------
__global__ void cvt_plain_k(const float* __restrict__ in,
                            uint16_t* __restrict__ hi, uint16_t* __restrict__ lo)
{
    size_t i4 = (size_t)blockIdx.x * 256 + threadIdx.x;   // one float4 each
    float4 a = *((const float4*)in + i4);
    uint32_t h0, l0, h1, l1;
    split2(a.x, a.y, h0, l0);
    split2(a.z, a.w, h1, l1);
    ((uint2*)hi)[i4] = make_uint2(h0, h1);
    ((uint2*)lo)[i4] = make_uint2(l0, l1);
}

// ---------------- pre-pass: pair-packed split (B matrices) ------------------
// out[k2][n] word = {bf16 elem(2*k2, n) low, bf16 elem(2*k2+1, n) high}
__global__ void cvt_pack_k(const float* __restrict__ in,   // (R, 4096)
                           uint32_t* __restrict__ hi, uint32_t* __restrict__ lo)
{
    size_t idx = (size_t)blockIdx.x * 256 + threadIdx.x;   // (k2, n-quad)
    int k2 = (int)(idx >> 10);
    int n4 = (int)(idx & 1023) << 2;
    float4 r0 = *(const float4*)(in + (size_t)(2 * k2) * NBC + n4);
    float4 r1 = *(const float4*)(in + (size_t)(2 * k2 + 1) * NBC + n4);
    uint4 ho, lw;
    split2(r0.x, r1.x, ho.x, lw.x);
    split2(r0.y, r1.y, ho.y, lw.y);
    split2(r0.z, r1.z, ho.z, lw.z);
    split2(r0.w, r1.w, ho.w, lw.w);
    *(uint4*)(hi + (size_t)k2 * NBC + n4) = ho;
    *(uint4*)(lo + (size_t)k2 * NBC + n4) = lw;
}

// ---------------------------------------------------------------------------
// D = Ag @ Bg via split-bf16 mma.sync (3 terms: hh + hl + lh), fused GLU(+max).
// BM=BN=128, BK=32 (96 chunks), 2-stage cp.async pipeline.
// ---------------------------------------------------------------------------
__global__ __launch_bounds__(256, 2) void mma_glu_k(
    const uint16_t* __restrict__ Ahi, const uint16_t* __restrict__ Alo, // (.,3072) bf16 band base
    const uint32_t* __restrict__ Bhi, const uint32_t* __restrict__ Blo, // (1536,4096) packed
    const float* __restrict__ W, const float* __restrict__ bias,
    const float* __restrict__ maxsrc, float* __restrict__ out)
{
    extern __shared__ float smem[];
    char* smc = (char*)smem;
    const uint32_t smb = s2u(smem);
    const int tid = threadIdx.x, lane = tid & 31, wid = tid >> 5;
    const int bx = blockIdx.x, by = blockIdx.y;
    const int wm = wid >> 2, wn = wid & 3;   // warp grid 2(m) x 4(n)

    // A ldmatrix addressing: lane bit3 -> +8 rows, bit4 -> +16B (validated R9)
    const int arow = (lane & 7) + ((lane >> 3) & 1) * 8;
    const int ab16 = ((lane >> 4) & 1) * 16;
    // base byte offsets (within stage) for the 4 m-frags of this warp, hi & lo
    uint32_t aoh[4], aol[4];
    #pragma unroll
    for (int mf = 0; mf < 4; mf++) {
        uint32_t ro = (wm * 64 + mf * 16 + arow) * A_PITCH + ab16;
        aoh[mf] = AHI_OFF + ro;
        aol[mf] = ALO_OFF + ro;
    }
    // B fragment word offsets (within stage, u32 units): b0 at k2=lane&3, b1 at +4
    const uint32_t bw0 = (lane & 3) * (B_PITCH / 4) + wn * 32 + (lane >> 2);

    // cp.async loaders
    const int am = tid >> 1, ap = tid & 1;            // A row, 32B-half
    const size_t aSrcOff = (size_t)(by * 128 + am) * KDIM + ap * 16;  // bf16 idx
    const uint32_t aDst = am * A_PITCH + ap * 32;
    const int bk2 = tid >> 4, bseg = tid & 15;        // B k2-row, 32B segment
    const size_t bSrcOff = (size_t)bx * 128 + bseg * 8;               // word idx
    const uint32_t bDst = bk2 * B_PITCH + bseg * 32;

    auto issue = [&](int c) {
        const uint32_t sb = smb + (c & 1) * STAGE_B;
        const uint16_t* ah = Ahi + aSrcOff + c * 32;
        const uint16_t* al = Alo + aSrcOff + c * 32;
        cpasync16(sb + AHI_OFF + aDst,      ah);
        cpasync16(sb + AHI_OFF + aDst + 16, ah + 8);
        cpasync16(sb + ALO_OFF + aDst,      al);
        cpasync16(sb + ALO_OFF + aDst + 16, al + 8);
        const uint32_t* bh = Bhi + bSrcOff + (size_t)(c * 16 + bk2) * NBC;
        const uint32_t* bl = Blo + bSrcOff + (size_t)(c * 16 + bk2) * NBC;
        cpasync16(sb + BHI_OFF + bDst,      bh);
        cpasync16(sb + BHI_OFF + bDst + 16, bh + 4);
        cpasync16(sb + BLO_OFF + bDst,      bl);
        cpasync16(sb + BLO_OFF + bDst + 16, bl + 4);
        asm volatile("cp.async.commit_group;");
    };

    float acc[4][4][4] = {};

    issue(0);
    for (int c = 0; c < 96; c++) {
        asm volatile("cp.async.wait_group 0;");
        __syncthreads();
        if (c < 95) issue(c + 1);

        const uint32_t sb = smb + (c & 1) * STAGE_B;
        const uint32_t* sw = (const uint32_t*)(smc + (c & 1) * STAGE_B);
        #pragma unroll
        for (int ks = 0; ks < 2; ks++) {
            // B frags for this k16: 4 n-frags, hi & lo
            uint32_t bh[4][2], bl[4][2];
            const uint32_t* bph = sw + BHI_OFF / 4 + ks * 8 * (B_PITCH / 4) + bw0;
            const uint32_t* bpl = sw + BLO_OFF / 4 + ks * 8 * (B_PITCH / 4) + bw0;
            #pragma unroll
            for (int f = 0; f < 4; f++) {
                bh[f][0] = bph[f * 8];
                bh[f][1] = bph[f * 8 + 4 * (B_PITCH / 4)];
                bl[f][0] = bpl[f * 8];
                bl[f][1] = bpl[f * 8 + 4 * (B_PITCH / 4)];
            }
            #pragma unroll
            for (int mg = 0; mg < 2; mg++) {
                uint32_t ah2[2][4], al2[2][4];
                #pragma unroll
                for (int i = 0; i < 2; i++) {
                    ldsm4(ah2[i], sb + aoh[mg * 2 + i] + ks * 32);
                    ldsm4(al2[i], sb + aol[mg * 2 + i] + ks * 32);
                }
                #pragma unroll
                for (int i = 0; i < 2; i++)
                    #pragma unroll
                    for (int f = 0; f < 4; f++) {
                        mma16(acc[mg * 2 + i][f], ah2[i], bh[f]);
                        mma16(acc[mg * 2 + i][f], ah2[i], bl[f]);
                        mma16(acc[mg * 2 + i][f], al2[i], bh[f]);
                    }
            }
        }
    }
    __syncthreads();

    // ---------------- fused GLU epilogue (validated R9/R11) -----------------
    // acc: c0,c1 = (row=lane>>2, n=(lane&3)*2+{0,1}), c2,c3 = row+8.
    float* gs = smem;                 // [p2 = local_row*2 + b2][c], pitch 68
    const int pair = tid >> 2;
    const int h0 = (tid & 3) << 4;
    const int vLoc = pair >> 1, b2r = pair & 1;

    #pragma unroll 1
    for (int ch = 0; ch < 4; ch++) {
        if (wm == (ch >> 1)) {
            #pragma unroll
            for (int gg = 0; gg < 2; gg++) {
                const int g = (ch & 1) * 2 + gg;
                #pragma unroll
                for (int f = 0; f < 4; f++) {
                    const int n0 = wn * 32 + f * 8 + (lane & 3) * 2;
                    const int b2 = n0 >> 6, cc = n0 & 63;
                    const int lr = gg * 16 + (lane >> 2);
                    *(float2*)&gs[(lr * 2 + b2) * 68 + cc] =
                        make_float2(acc[g][f][0], acc[g][f][1]);
                    *(float2*)&gs[((lr + 8) * 2 + b2) * 68 + cc] =
                        make_float2(acc[g][f][2], acc[g][f][3]);
                }
            }
        }
        __syncthreads();

        const float* grow = &gs[pair * 68];
        const size_t orow = (size_t)((by << 7) + (ch << 5) + vLoc) * NBC
                          + (bx << 7) + (b2r << 6);
        #pragma unroll 4
        for (int hq = 0; hq < 4; hq++) {
            float v4[4];
            #pragma unroll
            for (int hs = 0; hs < 4; hs++) {
                const int h = h0 + hq * 4 + hs;
                float accL = __ldg(&bias[h]);
                float accR = __ldg(&bias[h + 64]);
                const float4* wl = (const float4*)(W + h * 64);
                const float4* wr = (const float4*)(W + (h + 64) * 64);
                #pragma unroll
                for (int c4 = 0; c4 < 16; c4++) {
                    float4 g = *(const float4*)(grow + c4 * 4);
                    float4 a = __ldg(wl + c4), r = __ldg(wr + c4);
                    accL += a.x * g.x + a.y * g.y + a.z * g.z + a.w * g.w;
                    accR += r.x * g.x + r.y * g.y + r.z * g.z + r.w * g.w;
                }
                v4[hs] = __fdividef(accL, 1.0f + __expf(-accR));
            }
            if (maxsrc) {
                float4 m = *(const float4*)(maxsrc + orow + h0 + hq * 4);
                v4[0] = fmaxf(v4[0], m.x); v4[1] = fmaxf(v4[1], m.y);
                v4[2] = fmaxf(v4[2], m.z); v4[3] = fmaxf(v4[3], m.w);
            }
            *(float4*)(out + orow + h0 + hq * 4) = make_float4(v4[0], v4[1], v4[2], v4[3]);
        }
        __syncthreads();
    }
}

extern "C" void kernel_launch(void* const* d_in, const int* in_sizes, int n_in,
                              void* d_out, int out_size)
{
    const float* x  = (const float*)d_in[0];
    const float* A  = (const float*)d_in[1];
    const float* W0 = (const float*)d_in[2];
    const float* b0 = (const float*)d_in[3];
    const float* W1 = (const float*)d_in[4];
    const float* b1 = (const float*)d_in[5];
    float* out = (float*)d_out;

    uint16_t *Ahi = nullptr, *Alo = nullptr;
    uint32_t *Xhi = nullptr, *Xlo = nullptr, *H1hi = nullptr, *H1lo = nullptr;
    float* H1 = nullptr;
    cudaGetSymbolAddress((void**)&Ahi, g_Ahi);
    cudaGetSymbolAddress((void**)&Alo, g_Alo);
    cudaGetSymbolAddress((void**)&Xhi, g_Xhi);
    cudaGetSymbolAddress((void**)&Xlo, g_Xlo);
    cudaGetSymbolAddress((void**)&H1, g_H1);
    cudaGetSymbolAddress((void**)&H1hi, g_H1hi);
    cudaGetSymbolAddress((void**)&H1lo, g_H1lo);
    if (!Ahi || !Alo || !Xhi || !Xlo || !H1 || !H1hi || !H1lo) return;

    cudaFuncSetAttribute(mma_glu_k, cudaFuncAttributeMaxDynamicSharedMemorySize, SMEMB);

    cvt_plain_k<<<9216, 256>>>(A, Ahi, Alo);           // A -> hi/lo bf16
    cvt_pack_k<<<6144, 256>>>(x, Xhi, Xlo);            // X -> packed hi/lo
    mma_glu_k<<<dim3(32, 24), 256, SMEMB>>>(Ahi, Alo, Xhi, Xlo, W0, b0, nullptr, H1);
    cvt_pack_k<<<6144, 256>>>(H1, H1hi, H1lo);         // H1 -> packed hi/lo
    mma_glu_k<<<dim3(32, 8), 256, SMEMB>>>(Ahi + (size_t)NMID * KDIM,
                                           Alo + (size_t)NMID * KDIM,
                                           H1hi, H1lo, W1, b1,
                                           H1 + (size_t)NMID * NBC, out);
}

// round 13
// speedup vs baseline: 1.0202x; 1.0202x over previous
#include <cuda_runtime.h>
#include <cuda_fp16.h>
#include <cstdint>
#include <math.h>

#define KDIM 3072
#define NBC  4096
#define NMID 1024

// ---- stage geometry (bytes) ----
#define A_PITCH 80            // 32 fp16 = 64B data + 16B pad (ldsm conflict-free)
#define AHI_OFF 0
#define ALO_OFF 10240
#define B_OFF   20480
#define B_PITCH 544           // 128 words + 8 pad words (LDS conflict-free)
#define STAGE_B 29184         // 20480 + 16*544
#define NSTAGE  3
#define SMEMB   (STAGE_B * NSTAGE)   // 87552 bytes

// ---- scratch (no allocation allowed) ----
__device__ uint16_t g_Ahi[(size_t)3072 * 3072];
__device__ uint16_t g_Alo[(size_t)3072 * 3072];
__device__ uint32_t g_Xh [(size_t)1536 * 4096];   // pair-packed {k even, k odd} fp16
__device__ float    g_H1 [(size_t)3072 * 4096];
__device__ uint32_t g_H1h[(size_t)1536 * 4096];

__device__ __forceinline__ uint32_t s2u(const void* p) {
    uint32_t a;
    asm("{\n.reg .u64 t;\ncvta.to.shared.u64 t,%1;\ncvt.u32.u64 %0,t;\n}" : "=r"(a) : "l"(p));
    return a;
}
__device__ __forceinline__ void ldsm4(uint32_t* r, uint32_t addr) {
    asm volatile("ldmatrix.sync.aligned.m8n8.x4.shared.b16 {%0,%1,%2,%3},[%4];"
                 : "=r"(r[0]), "=r"(r[1]), "=r"(r[2]), "=r"(r[3]) : "r"(addr));
}
__device__ __forceinline__ void mma16(float* d, const uint32_t* a, const uint32_t* b) {
    asm volatile("mma.sync.aligned.m16n8k16.row.col.f32.f16.f16.f32 "
                 "{%0,%1,%2,%3},{%4,%5,%6,%7},{%8,%9},{%0,%1,%2,%3};"
                 : "+f"(d[0]), "+f"(d[1]), "+f"(d[2]), "+f"(d[3])
                 : "r"(a[0]), "r"(a[1]), "r"(a[2]), "r"(a[3]), "r"(b[0]), "r"(b[1]));
}
__device__ __forceinline__ void cpasync16(uint32_t dst, const void* src) {
    asm volatile("cp.async.cg.shared.global [%0],[%1],16;" :: "r"(dst), "l"(src));
}
__device__ __forceinline__ void splitA1(float x, uint16_t& hi, uint16_t& lo) {
    __half h = __float2half_rn(x);
    float r = x - __half2float(h);
    __half l = __float2half_rn(r);
    hi = *reinterpret_cast<uint16_t*>(&h);
    lo = *reinterpret_cast<uint16_t*>(&l);
}

// ---------------- pre-pass: A -> fp16 hi/lo -------------------------------
__global__ void cvt_splitA_k(const float* __restrict__ in,
                             uint16_t* __restrict__ hi, uint16_t* __restrict__ lo)
{
    size_t i4 = (size_t)blockIdx.x * 256 + threadIdx.x;   // one float4 each
    float4 a = *((const float4*)in + i4);
    uint16_t h[4], l[4];
    splitA1(a.x, h[0], l[0]);
    splitA1(a.y, h[1], l[1]);
    splitA1(a.z, h[2], l[2]);
    splitA1(a.w, h[3], l[3]);
    ((uint2*)hi)[i4] = make_uint2((uint32_t)h[0] | ((uint32_t)h[1] << 16),
                                  (uint32_t)h[2] | ((uint32_t)h[3] << 16));
    ((uint2*)lo)[i4] = make_uint2((uint32_t)l[0] | ((uint32_t)l[1] << 16),
                                  (uint32_t)l[2] | ((uint32_t)l[3] << 16));
}

// ---------------- pre-pass: B -> pair-packed fp16 -------------------------
// out[k2][n] word = half2{ in(2*k2, n), in(2*k2+1, n) }
__global__ void cvt_packB_k(const float* __restrict__ in,   // (R, 4096)
                            uint32_t* __restrict__ o)
{
    size_t idx = (size_t)blockIdx.x * 256 + threadIdx.x;   // (k2, n-quad)
    int k2 = (int)(idx >> 10);
    int n4 = (int)(idx & 1023) << 2;
    float4 r0 = *(const float4*)(in + (size_t)(2 * k2) * NBC + n4);
    float4 r1 = *(const float4*)(in + (size_t)(2 * k2 + 1) * NBC + n4);
    __half2 w0 = __floats2half2_rn(r0.x, r1.x);   // .x low half
    __half2 w1 = __floats2half2_rn(r0.y, r1.y);
    __half2 w2 = __floats2half2_rn(r0.z, r1.z);
    __half2 w3 = __floats2half2_rn(r0.w, r1.w);
    uint4 v;
    v.x = *reinterpret_cast<uint32_t*>(&w0);
    v.y = *reinterpret_cast<uint32_t*>(&w1);
    v.z = *reinterpret_cast<uint32_t*>(&w2);
    v.w = *reinterpret_cast<uint32_t*>(&w3);
    *(uint4*)(o + (size_t)k2 * NBC + n4) = v;
}

// ---------------------------------------------------------------------------
// D = Ag @ Bg via 2-term fp16 mma.sync (Ah*B + Al*B), fused GLU(+max).
// BM=BN=128, BK=32 (96 chunks), 3-stage cp.async pipeline, prefetch dist 2.
// ---------------------------------------------------------------------------
__global__ __launch_bounds__(256, 2) void mma_glu_k(
    const uint16_t* __restrict__ Ahi, const uint16_t* __restrict__ Alo, // (.,3072) band base
    const uint32_t* __restrict__ Bp,  // (1536, 4096) pair-packed fp16
    const float* __restrict__ W, const float* __restrict__ bias,
    const float* __restrict__ maxsrc, float* __restrict__ out)
{
    extern __shared__ float smem[];
    char* smc = (char*)smem;
    const uint32_t smb = s2u(smem);
    const int tid = threadIdx.x, lane = tid & 31, wid = tid >> 5;
    const int bx = blockIdx.x, by = blockIdx.y;
    const int wm = wid >> 2, wn = wid & 3;   // warp grid 2(m) x 4(n)

    // A ldmatrix addressing (validated): lane bit3 -> +8 rows, bit4 -> +16B
    const int arow = (lane & 7) + ((lane >> 3) & 1) * 8;
    const int ab16 = ((lane >> 4) & 1) * 16;
    uint32_t aoh[4], aol[4];
    #pragma unroll
    for (int mf = 0; mf < 4; mf++) {
        uint32_t ro = (wm * 64 + mf * 16 + arow) * A_PITCH + ab16;
        aoh[mf] = AHI_OFF + ro;
        aol[mf] = ALO_OFF + ro;
    }
    // B fragment word offset: b0 at k2=lane&3, b1 at k2+4 (within ks block)
    const uint32_t bw0 = (lane & 3) * (B_PITCH / 4) + wn * 32 + (lane >> 2);

    // cp.async loaders
    const int am = tid >> 1, ap = tid & 1;            // A row, 32B-half
    const size_t aSrcOff = (size_t)(by * 128 + am) * KDIM + ap * 16;  // fp16 idx
    const uint32_t aDst = am * A_PITCH + ap * 32;
    const int bk2 = tid >> 4, bseg = tid & 15;        // B k2-row, 32B segment
    const size_t bSrcOff = (size_t)bx * 128 + bseg * 8;               // word idx
    const uint32_t bDst = B_OFF + bk2 * B_PITCH + bseg * 32;

    auto issue = [&](int c) {
        const uint32_t sb = smb + (uint32_t)((c % NSTAGE) * STAGE_B);
        const uint16_t* ah = Ahi + aSrcOff + c * 32;
        const uint16_t* al = Alo + aSrcOff + c * 32;
        cpasync16(sb + AHI_OFF + aDst,      ah);
        cpasync16(sb + AHI_OFF + aDst + 16, ah + 8);
        cpasync16(sb + ALO_OFF + aDst,      al);
        cpasync16(sb + ALO_OFF + aDst + 16, al + 8);
        const uint32_t* bp = Bp + bSrcOff + (size_t)(c * 16 + bk2) * NBC;
        cpasync16(sb + bDst,      bp);
        cpasync16(sb + bDst + 16, bp + 4);
        asm volatile("cp.async.commit_group;");
    };

    float acc[4][4][4] = {};

    issue(0);
    issue(1);
    for (int c = 0; c < 96; c++) {
        asm volatile("cp.async.wait_group 1;");
        __syncthreads();
        if (c < 94) issue(c + 2);

        const int slot = c % NSTAGE;
        const uint32_t sb = smb + (uint32_t)(slot * STAGE_B);
        const uint32_t* sw = (const uint32_t*)(smc + slot * STAGE_B);
        #pragma unroll
        for (int ks = 0; ks < 2; ks++) {
            uint32_t bfr[4][2];
            const uint32_t* bpw = sw + B_OFF / 4 + ks * 8 * (B_PITCH / 4) + bw0;
            #pragma unroll
            for (int f = 0; f < 4; f++) {
                bfr[f][0] = bpw[f * 8];
                bfr[f][1] = bpw[f * 8 + 4 * (B_PITCH / 4)];
            }
            #pragma unroll
            for (int mg = 0; mg < 2; mg++) {
                uint32_t ah2[2][4], al2[2][4];
                #pragma unroll
                for (int i = 0; i < 2; i++) {
                    ldsm4(ah2[i], sb + aoh[mg * 2 + i] + ks * 32);
                    ldsm4(al2[i], sb + aol[mg * 2 + i] + ks * 32);
                }
                #pragma unroll
                for (int i = 0; i < 2; i++)
                    #pragma unroll
                    for (int f = 0; f < 4; f++) {
                        mma16(acc[mg * 2 + i][f], ah2[i], bfr[f]);
                        mma16(acc[mg * 2 + i][f], al2[i], bfr[f]);
                    }
            }
        }
    }
    __syncthreads();

    // ---------------- fused GLU epilogue (validated) ------------------------
    // acc: c0,c1 = (row=lane>>2, n=(lane&3)*2+{0,1}), c2,c3 = row+8.
    float* gs = smem;                 // [p2 = local_row*2 + b2][c], pitch 68
    const int pair = tid >> 2;
    const int h0 = (tid & 3) << 4;
    const int vLoc = pair >> 1, b2r = pair & 1;

    #pragma unroll 1
    for (int ch = 0; ch < 4; ch++) {
        if (wm == (ch >> 1)) {
            #pragma unroll
            for (int gg = 0; gg < 2; gg++) {
                const int g = (ch & 1) * 2 + gg;
                #pragma unroll
                for (int f = 0; f < 4; f++) {
                    const int n0 = wn * 32 + f * 8 + (lane & 3) * 2;
                    const int b2 = n0 >> 6, cc = n0 & 63;
                    const int lr = gg * 16 + (lane >> 2);
                    *(float2*)&gs[(lr * 2 + b2) * 68 + cc] =
                        make_float2(acc[g][f][0], acc[g][f][1]);
                    *(float2*)&gs[((lr + 8) * 2 + b2) * 68 + cc] =
                        make_float2(acc[g][f][2], acc[g][f][3]);
                }
            }
        }
        __syncthreads();

        const float* grow = &gs[pair * 68];
        const size_t orow = (size_t)((by << 7) + (ch << 5) + vLoc) * NBC
                          + (bx << 7) + (b2r << 6);
        #pragma unroll 4
        for (int hq = 0; hq < 4; hq++) {
            float v4[4];
            #pragma unroll
            for (int hs = 0; hs < 4; hs++) {
                const int h = h0 + hq * 4 + hs;
                float accL = __ldg(&bias[h]);
                float accR = __ldg(&bias[h + 64]);
                const float4* wl = (const float4*)(W + h * 64);
                const float4* wr = (const float4*)(W + (h + 64) * 64);
                #pragma unroll
                for (int c4 = 0; c4 < 16; c4++) {
                    float4 g = *(const float4*)(grow + c4 * 4);
                    float4 a = __ldg(wl + c4), r = __ldg(wr + c4);
                    accL += a.x * g.x + a.y * g.y + a.z * g.z + a.w * g.w;
                    accR += r.x * g.x + r.y * g.y + r.z * g.z + r.w * g.w;
                }
                v4[hs] = __fdividef(accL, 1.0f + __expf(-accR));
            }
            if (maxsrc) {
                float4 m = *(const float4*)(maxsrc + orow + h0 + hq * 4);
                v4[0] = fmaxf(v4[0], m.x); v4[1] = fmaxf(v4[1], m.y);
                v4[2] = fmaxf(v4[2], m.z); v4[3] = fmaxf(v4[3], m.w);
            }
            *(float4*)(out + orow + h0 + hq * 4) = make_float4(v4[0], v4[1], v4[2], v4[3]);
        }
        __syncthreads();
    }
}

extern "C" void kernel_launch(void* const* d_in, const int* in_sizes, int n_in,
                              void* d_out, int out_size)
{
    const float* x  = (const float*)d_in[0];
    const float* A  = (const float*)d_in[1];
    const float* W0 = (const float*)d_in[2];
    const float* b0 = (const float*)d_in[3];
    const float* W1 = (const float*)d_in[4];
    const float* b1 = (const float*)d_in[5];
    float* out = (float*)d_out;

    uint16_t *Ahi = nullptr, *Alo = nullptr;
    uint32_t *Xh = nullptr, *H1h = nullptr;
    float* H1 = nullptr;
    cudaGetSymbolAddress((void**)&Ahi, g_Ahi);
    cudaGetSymbolAddress((void**)&Alo, g_Alo);
    cudaGetSymbolAddress((void**)&Xh, g_Xh);
    cudaGetSymbolAddress((void**)&H1, g_H1);
    cudaGetSymbolAddress((void**)&H1h, g_H1h);
    if (!Ahi || !Alo || !Xh || !H1 || !H1h) return;

    cudaFuncSetAttribute(mma_glu_k, cudaFuncAttributeMaxDynamicSharedMemorySize, SMEMB);

    cvt_splitA_k<<<9216, 256>>>(A, Ahi, Alo);          // A -> fp16 hi/lo
    cvt_packB_k<<<6144, 256>>>(x, Xh);                 // X -> packed fp16
    mma_glu_k<<<dim3(32, 24), 256, SMEMB>>>(Ahi, Alo, Xh, W0, b0, nullptr, H1);
    cvt_packB_k<<<6144, 256>>>(H1, H1h);               // H1 -> packed fp16
    mma_glu_k<<<dim3(32, 8), 256, SMEMB>>>(Ahi + (size_t)NMID * KDIM,
                                           Alo + (size_t)NMID * KDIM,
                                           H1h, W1, b1,
                                           H1 + (size_t)NMID * NBC, out);
}

// round 14
// speedup vs baseline: 1.6947x; 1.6612x over previous
#include <cuda_runtime.h>
#include <cuda_fp16.h>
#include <cstdint>
#include <math.h>

#define KDIM 3072
#define NBC  4096
#define NMID 1024

// ---- stage geometry (bytes) ----
#define A_PITCH 144           // 64 fp16 = 128B data + 16B pad (ldsm conflict-free)
#define B_OFF   18432         // A region = 128*144
#define B_PITCH 544           // 128 words + 8 pad words (LDS conflict-free)
#define STAGE_B 35840         // 18432 + 32*544
#define NSTAGE  3
#define SMEMB   (STAGE_B * NSTAGE)   // 107520 bytes

// ---- scratch (no allocation allowed) ----
__device__ uint16_t g_Ah [(size_t)3072 * 3072];   // A in fp16
__device__ uint32_t g_Xh [(size_t)1536 * 4096];   // X pair-packed {k even, k odd} fp16
__device__ float    g_H1 [(size_t)3072 * 4096];
__device__ uint32_t g_H1h[(size_t)1536 * 4096];

__device__ __forceinline__ uint32_t s2u(const void* p) {
    uint32_t a;
    asm("{\n.reg .u64 t;\ncvta.to.shared.u64 t,%1;\ncvt.u32.u64 %0,t;\n}" : "=r"(a) : "l"(p));
    return a;
}
__device__ __forceinline__ void ldsm4(uint32_t* r, uint32_t addr) {
    asm volatile("ldmatrix.sync.aligned.m8n8.x4.shared.b16 {%0,%1,%2,%3},[%4];"
                 : "=r"(r[0]), "=r"(r[1]), "=r"(r[2]), "=r"(r[3]) : "r"(addr));
}
__device__ __forceinline__ void mma16(float* d, const uint32_t* a, const uint32_t* b) {
    asm volatile("mma.sync.aligned.m16n8k16.row.col.f32.f16.f16.f32 "
                 "{%0,%1,%2,%3},{%4,%5,%6,%7},{%8,%9},{%0,%1,%2,%3};"
                 : "+f"(d[0]), "+f"(d[1]), "+f"(d[2]), "+f"(d[3])
                 : "r"(a[0]), "r"(a[1]), "r"(a[2]), "r"(a[3]), "r"(b[0]), "r"(b[1]));
}
__device__ __forceinline__ void cpasync16(uint32_t dst, const void* src) {
    asm volatile("cp.async.cg.shared.global [%0],[%1],16;" :: "r"(dst), "l"(src));
}

// ---------------- pre-pass: A -> fp16 --------------------------------------
__global__ void cvt_A_k(const float* __restrict__ in, uint16_t* __restrict__ o)
{
    size_t i4 = (size_t)blockIdx.x * 256 + threadIdx.x;   // one float4 each
    float4 a = *((const float4*)in + i4);
    __half2 lo = __floats2half2_rn(a.x, a.y);
    __half2 hi = __floats2half2_rn(a.z, a.w);
    ((uint2*)o)[i4] = make_uint2(*reinterpret_cast<uint32_t*>(&lo),
                                 *reinterpret_cast<uint32_t*>(&hi));
}

// ---------------- pre-pass: B -> pair-packed fp16 -------------------------
// out[k2][n] word = half2{ in(2*k2, n), in(2*k2+1, n) }
__global__ void cvt_packB_k(const float* __restrict__ in,   // (R, 4096)
                            uint32_t* __restrict__ o)
{
    size_t idx = (size_t)blockIdx.x * 256 + threadIdx.x;   // (k2, n-quad)
    int k2 = (int)(idx >> 10);
    int n4 = (int)(idx & 1023) << 2;
    float4 r0 = *(const float4*)(in + (size_t)(2 * k2) * NBC + n4);
    float4 r1 = *(const float4*)(in + (size_t)(2 * k2 + 1) * NBC + n4);
    __half2 w0 = __floats2half2_rn(r0.x, r1.x);   // .x low half
    __half2 w1 = __floats2half2_rn(r0.y, r1.y);
    __half2 w2 = __floats2half2_rn(r0.z, r1.z);
    __half2 w3 = __floats2half2_rn(r0.w, r1.w);
    uint4 v;
    v.x = *reinterpret_cast<uint32_t*>(&w0);
    v.y = *reinterpret_cast<uint32_t*>(&w1);
    v.z = *reinterpret_cast<uint32_t*>(&w2);
    v.w = *reinterpret_cast<uint32_t*>(&w3);
    *(uint4*)(o + (size_t)k2 * NBC + n4) = v;
}

// ---------------------------------------------------------------------------
// D = Ag @ Bg via single-term fp16 mma.sync, fused GLU(+max).
// BM=BN=128, BK=64 (48 iterations), 3-stage cp.async pipeline, prefetch 2.
// ---------------------------------------------------------------------------
__global__ __launch_bounds__(256, 2) void mma_glu_k(
    const uint16_t* __restrict__ Ah,  // (Mrows, 3072) fp16 band base
    const uint32_t* __restrict__ Bp,  // (1536, 4096) pair-packed fp16
    const float* __restrict__ W, const float* __restrict__ bias,
    const float* __restrict__ maxsrc, float* __restrict__ out)
{
    extern __shared__ float smem[];
    char* smc = (char*)smem;
    const uint32_t smb = s2u(smem);
    const int tid = threadIdx.x, lane = tid & 31, wid = tid >> 5;
    const int bx = blockIdx.x, by = blockIdx.y;
    const int wm = wid >> 2, wn = wid & 3;   // warp grid 2(m) x 4(n)

    // A ldmatrix addressing (validated): lane bit3 -> +8 rows, bit4 -> +16B
    const int arow = (lane & 7) + ((lane >> 3) & 1) * 8;
    const int ab16 = ((lane >> 4) & 1) * 16;
    uint32_t aoff[4];
    #pragma unroll
    for (int mf = 0; mf < 4; mf++)
        aoff[mf] = (wm * 64 + mf * 16 + arow) * A_PITCH + ab16;

    // B fragment word offset within k16-slab: b0 at k2=lane&3, b1 at +4 rows
    const uint32_t bw0 = (lane & 3) * (B_PITCH / 4) + wn * 32 + (lane >> 2);

    // cp.async loaders (per BK=64 iter: A 16KB, B 16KB, 8x16B per thread)
    const int am = tid & 127, ah2 = tid >> 7;         // A row, 64B-half
    const size_t aSrcOff = (size_t)(by * 128 + am) * KDIM + ah2 * 32;  // fp16 idx
    const uint32_t aDst = am * A_PITCH + ah2 * 64;
    const int bk2 = tid >> 3, bseg = tid & 7;         // B k2-row (0..31), 64B seg
    const size_t bSrcOff = (size_t)bx * 128 + bseg * 16;               // word idx
    const uint32_t bDst = B_OFF + bk2 * B_PITCH + bseg * 64;

    auto issue = [&](int i) {
        const uint32_t sb = smb + (uint32_t)((i % NSTAGE) * STAGE_B);
        const uint16_t* ap = Ah + aSrcOff + i * 64;
        #pragma unroll
        for (int j = 0; j < 4; j++)
            cpasync16(sb + aDst + j * 16, ap + j * 8);
        const uint32_t* bp = Bp + bSrcOff + (size_t)(i * 32 + bk2) * NBC;
        #pragma unroll
        for (int j = 0; j < 4; j++)
            cpasync16(sb + bDst + j * 16, bp + j * 4);
        asm volatile("cp.async.commit_group;");
    };

    float acc[4][4][4] = {};

    issue(0);
    issue(1);
    for (int i = 0; i < 48; i++) {
        asm volatile("cp.async.wait_group 1;");
        __syncthreads();
        if (i < 46) issue(i + 2);

        const int slot = i % NSTAGE;
        const uint32_t sb = smb + (uint32_t)(slot * STAGE_B);
        const uint32_t* sw = (const uint32_t*)(smc + slot * STAGE_B);
        #pragma unroll
        for (int ks = 0; ks < 4; ks++) {
            uint32_t bfr[4][2];
            const uint32_t* bpw = sw + B_OFF / 4 + ks * 8 * (B_PITCH / 4) + bw0;
            #pragma unroll
            for (int f = 0; f < 4; f++) {
                bfr[f][0] = bpw[f * 8];
                bfr[f][1] = bpw[f * 8 + 4 * (B_PITCH / 4)];
            }
            uint32_t afr[4][4];
            #pragma unroll
            for (int mf = 0; mf < 4; mf++)
                ldsm4(afr[mf], sb + aoff[mf] + ks * 32);
            #pragma unroll
            for (int mf = 0; mf < 4; mf++)
                #pragma unroll
                for (int f = 0; f < 4; f++)
                    mma16(acc[mf][f], afr[mf], bfr[f]);
        }
    }
    __syncthreads();

    // ---------------- fused GLU epilogue (validated) ------------------------
    // acc: c0,c1 = (row=lane>>2, n=(lane&3)*2+{0,1}), c2,c3 = row+8.
    float* gs = smem;                 // [p2 = local_row*2 + b2][c], pitch 68
    const int pair = tid >> 2;
    const int h0 = (tid & 3) << 4;
    const int vLoc = pair >> 1, b2r = pair & 1;

    #pragma unroll 1
    for (int ch = 0; ch < 4; ch++) {
        if (wm == (ch >> 1)) {
            #pragma unroll
            for (int gg = 0; gg < 2; gg++) {
                const int g = (ch & 1) * 2 + gg;
                #pragma unroll
                for (int f = 0; f < 4; f++) {
                    const int n0 = wn * 32 + f * 8 + (lane & 3) * 2;
                    const int b2 = n0 >> 6, cc = n0 & 63;
                    const int lr = gg * 16 + (lane >> 2);
                    *(float2*)&gs[(lr * 2 + b2) * 68 + cc] =
                        make_float2(acc[g][f][0], acc[g][f][1]);
                    *(float2*)&gs[((lr + 8) * 2 + b2) * 68 + cc] =
                        make_float2(acc[g][f][2], acc[g][f][3]);
                }
            }
        }
        __syncthreads();

        const float* grow = &gs[pair * 68];
        const size_t orow = (size_t)((by << 7) + (ch << 5) + vLoc) * NBC
                          + (bx << 7) + (b2r << 6);
        #pragma unroll 4
        for (int hq = 0; hq < 4; hq++) {
            float v4[4];
            #pragma unroll
            for (int hs = 0; hs < 4; hs++) {
                const int h = h0 + hq * 4 + hs;
                float accL = __ldg(&bias[h]);
                float accR = __ldg(&bias[h + 64]);
                const float4* wl = (const float4*)(W + h * 64);
                const float4* wr = (const float4*)(W + (h + 64) * 64);
                #pragma unroll
                for (int c4 = 0; c4 < 16; c4++) {
                    float4 g = *(const float4*)(grow + c4 * 4);
                    float4 a = __ldg(wl + c4), r = __ldg(wr + c4);
                    accL += a.x * g.x + a.y * g.y + a.z * g.z + a.w * g.w;
                    accR += r.x * g.x + r.y * g.y + r.z * g.z + r.w * g.w;
                }
                v4[hs] = __fdividef(accL, 1.0f + __expf(-accR));
            }
            if (maxsrc) {
                float4 m = *(const float4*)(maxsrc + orow + h0 + hq * 4);
                v4[0] = fmaxf(v4[0], m.x); v4[1] = fmaxf(v4[1], m.y);
                v4[2] = fmaxf(v4[2], m.z); v4[3] = fmaxf(v4[3], m.w);
            }
            *(float4*)(out + orow + h0 + hq * 4) = make_float4(v4[0], v4[1], v4[2], v4[3]);
        }
        __syncthreads();
    }
}

extern "C" void kernel_launch(void* const* d_in, const int* in_sizes, int n_in,
                              void* d_out, int out_size)
{
    const float* x  = (const float*)d_in[0];
    const float* A  = (const float*)d_in[1];
    const float* W0 = (const float*)d_in[2];
    const float* b0 = (const float*)d_in[3];
    const float* W1 = (const float*)d_in[4];
    const float* b1 = (const float*)d_in[5];
    float* out = (float*)d_out;

    uint16_t* Ah = nullptr;
    uint32_t *Xh = nullptr, *H1h = nullptr;
    float* H1 = nullptr;
    cudaGetSymbolAddress((void**)&Ah, g_Ah);
    cudaGetSymbolAddress((void**)&Xh, g_Xh);
    cudaGetSymbolAddress((void**)&H1, g_H1);
    cudaGetSymbolAddress((void**)&H1h, g_H1h);
    if (!Ah || !Xh || !H1 || !H1h) return;

    cudaFuncSetAttribute(mma_glu_k, cudaFuncAttributeMaxDynamicSharedMemorySize, SMEMB);

    cvt_A_k<<<9216, 256>>>(A, Ah);                     // A -> fp16
    cvt_packB_k<<<6144, 256>>>(x, Xh);                 // X -> packed fp16
    mma_glu_k<<<dim3(32, 24), 256, SMEMB>>>(Ah, Xh, W0, b0, nullptr, H1);
    cvt_packB_k<<<6144, 256>>>(H1, H1h);               // H1 -> packed fp16
    mma_glu_k<<<dim3(32, 8), 256, SMEMB>>>(Ah + (size_t)NMID * KDIM,
                                           H1h, W1, b1,
                                           H1 + (size_t)NMID * NBC, out);
}

// round 15
// speedup vs baseline: 1.9416x; 1.1457x over previous
#include <cuda_runtime.h>
#include <cuda_fp16.h>
#include <cstdint>
#include <math.h>

#define KDIM 3072
#define NBC  4096
#define NMID 1024

#define STAGE_B 32768                 // A 16KB + B 16KB
#define NSTAGE  3
#define SMEMB   (128 + NSTAGE * STAGE_B)   // 98432 bytes

// ---- scratch: tile-contiguous, swizzled fp16 operands ----------------------
// A: [band 0..23][chunk 0..47] -> 16KB block = 128 rows x 128B (SW128-swizzled)
__device__ uint16_t g_Ah [(size_t)3072 * 3072];
// B: [bx 0..31][chunk 0..47] -> 16KB block = 32 k2-rows x 512B (word-XOR swizzled)
__device__ uint32_t g_Xh [(size_t)1536 * 4096];
__device__ float    g_H1 [(size_t)3072 * 4096];
__device__ uint32_t g_H1h[(size_t)1536 * 4096];

__device__ __forceinline__ uint32_t s2u(const void* p) {
    uint32_t a;
    asm("{\n.reg .u64 t;\ncvta.to.shared.u64 t,%1;\ncvt.u32.u64 %0,t;\n}" : "=r"(a) : "l"(p));
    return a;
}
__device__ __forceinline__ void ldsm4(uint32_t* r, uint32_t addr) {
    asm volatile("ldmatrix.sync.aligned.m8n8.x4.shared.b16 {%0,%1,%2,%3},[%4];"
                 : "=r"(r[0]), "=r"(r[1]), "=r"(r[2]), "=r"(r[3]) : "r"(addr));
}
__device__ __forceinline__ void mma16(float* d, const uint32_t* a, const uint32_t* b) {
    asm volatile("mma.sync.aligned.m16n8k16.row.col.f32.f16.f16.f32 "
                 "{%0,%1,%2,%3},{%4,%5,%6,%7},{%8,%9},{%0,%1,%2,%3};"
                 : "+f"(d[0]), "+f"(d[1]), "+f"(d[2]), "+f"(d[3])
                 : "r"(a[0]), "r"(a[1]), "r"(a[2]), "r"(a[3]), "r"(b[0]), "r"(b[1]));
}
__device__ __forceinline__ void mbar_wait(uint32_t mbar, uint32_t phase) {
    uint32_t d = 0;
    do {
        asm volatile("{\n.reg .pred p;\n"
            "mbarrier.try_wait.parity.acquire.cta.shared::cta.b64 p,[%1],%2,0x989680;\n"
            "selp.b32 %0,1,0,p;\n}" : "=r"(d) : "r"(mbar), "r"(phase) : "memory");
    } while (!d);
}

// ---------------- pre-pass: A -> fp16, tiled + SW128-swizzled ---------------
__global__ void cvt_A_k(const float* __restrict__ in, uint16_t* __restrict__ o)
{
    size_t i4 = (size_t)blockIdx.x * 256 + threadIdx.x;   // one float4 each
    float4 a = *((const float4*)in + i4);
    __half2 lo = __floats2half2_rn(a.x, a.y);
    __half2 hi = __floats2half2_rn(a.z, a.w);
    int row = (int)(i4 / 768);
    int c4  = (int)(i4 % 768) * 4;
    int band = row >> 7, r = row & 127, chunk = c4 >> 6, c = c4 & 63;
    size_t blk = (size_t)(band * 48 + chunk) * 16384;     // bytes
    uint32_t off = (uint32_t)(r * 128 + c * 2);
    uint32_t so = off ^ ((off >> 3) & 0x70);              // SW128
    *(uint2*)((char*)o + blk + so) = make_uint2(*reinterpret_cast<uint32_t*>(&lo),
                                                *reinterpret_cast<uint32_t*>(&hi));
}

// ---------------- pre-pass: B -> pair-packed fp16, tiled + swizzled ---------
// block (bx, chunk): 32 k2-rows x 128 words; word w stored at w ^ ((k2&3)<<3)
__global__ void cvt_packB_k(const float* __restrict__ in,   // (R, 4096)
                            uint32_t* __restrict__ o)
{
    size_t idx = (size_t)blockIdx.x * 256 + threadIdx.x;   // (k2, n-quad)
    int k2 = (int)(idx >> 10);
    int n4 = (int)(idx & 1023) << 2;
    float4 r0 = *(const float4*)(in + (size_t)(2 * k2) * NBC + n4);
    float4 r1 = *(const float4*)(in + (size_t)(2 * k2 + 1) * NBC + n4);
    __half2 w0 = __floats2half2_rn(r0.x, r1.x);   // .x low half
    __half2 w1 = __floats2half2_rn(r0.y, r1.y);
    __half2 w2 = __floats2half2_rn(r0.z, r1.z);
    __half2 w3 = __floats2half2_rn(r0.w, r1.w);
    uint4 v;
    v.x = *reinterpret_cast<uint32_t*>(&w0);
    v.y = *reinterpret_cast<uint32_t*>(&w1);
    v.z = *reinterpret_cast<uint32_t*>(&w2);
    v.w = *reinterpret_cast<uint32_t*>(&w3);
    int bx = n4 >> 7, w = n4 & 127, chunk = k2 >> 5, k2l = k2 & 31;
    uint32_t wp = (uint32_t)w ^ ((uint32_t)(k2l & 3) << 3);
    size_t dst = (size_t)(bx * 48 + chunk) * 4096 + k2l * 128 + wp;   // words
    *(uint4*)(o + dst) = v;
}

// ---------------------------------------------------------------------------
// D = Ag @ Bg via fp16 mma.sync, bulk-copy fed (cp.async.bulk + mbarrier),
// fused GLU(+max). BM=BN=128, BK=64, 48 iters, 3-stage pipeline.
// ---------------------------------------------------------------------------
__global__ __launch_bounds__(256, 2) void mma_glu_k(
    const uint16_t* __restrict__ Ablk, // band-tiled blocks, base of this band set
    const uint32_t* __restrict__ Bblk, // (bx,chunk)-tiled blocks
    const float* __restrict__ W, const float* __restrict__ bias,
    const float* __restrict__ maxsrc, float* __restrict__ out)
{
    extern __shared__ float smem[];
    char* smc = (char*)smem;
    const uint32_t smb = s2u(smem);
    const int tid = threadIdx.x, lane = tid & 31, wid = tid >> 5;
    const int bx = blockIdx.x, by = blockIdx.y;
    const int wm = wid >> 2, wn = wid & 3;   // warp grid 2(m) x 4(n)

    if (tid == 0) {
        #pragma unroll
        for (int s = 0; s < NSTAGE; s++)
            asm volatile("mbarrier.init.shared.b64 [%0], %1;"
                         :: "r"(smb + 16 * s), "r"(1) : "memory");
    }
    asm volatile("fence.proxy.async.shared::cta;" ::: "memory");
    __syncthreads();

    // A ldsm addressing: row = wm*64+mf*16+arow; swizzle mask = (lane&7)<<4
    const int arow = (lane & 7) + ((lane >> 3) & 1) * 8;
    const int ab16 = ((lane >> 4) & 1) * 16;
    const uint32_t amask = (uint32_t)(lane & 7) << 4;
    uint32_t abase[4];
    #pragma unroll
    for (int mf = 0; mf < 4; mf++)
        abase[mf] = (uint32_t)((wm * 64 + mf * 16 + arow) * 128);

    // B word offsets (within B region) pre-XORed per f
    const uint32_t bmask = (uint32_t)(lane & 3) << 3;
    uint32_t wf[4];
    #pragma unroll
    for (int f = 0; f < 4; f++)
        wf[f] = ((uint32_t)(wn * 32 + f * 8 + (lane >> 2))) ^ bmask;

    auto issue = [&](int i) {
        if (tid == 0) {
            const int slot = i % NSTAGE;
            const uint32_t mbar = smb + 16 * slot;
            const uint32_t dst = smb + 128 + slot * STAGE_B;
            asm volatile("mbarrier.arrive.expect_tx.shared.b64 _, [%0], %1;"
                         :: "r"(mbar), "r"(2 * 16384) : "memory");
            const void* asrc = (const char*)Ablk + (size_t)(by * 48 + i) * 16384;
            const void* bsrc = (const char*)Bblk + (size_t)(bx * 48 + i) * 16384;
            asm volatile("cp.async.bulk.shared::cta.global.mbarrier::complete_tx::bytes "
                         "[%0], [%1], %2, [%3];"
                         :: "r"(dst), "l"(asrc), "r"(16384), "r"(mbar) : "memory");
            asm volatile("cp.async.bulk.shared::cta.global.mbarrier::complete_tx::bytes "
                         "[%0], [%1], %2, [%3];"
                         :: "r"(dst + 16384), "l"(bsrc), "r"(16384), "r"(mbar) : "memory");
        }
    };

    float acc[4][4][4] = {};

    issue(0);
    issue(1);
    for (int i = 0; i < 48; i++) {
        const int slot = i % NSTAGE;
        mbar_wait(smb + 16 * slot, (uint32_t)(i / 3) & 1);
        __syncthreads();
        if (i < 46) issue(i + 2);

        const uint32_t sa = smb + 128 + slot * STAGE_B;
        const uint32_t* bw = (const uint32_t*)(smc + 128 + slot * STAGE_B + 16384);
        #pragma unroll
        for (int ks = 0; ks < 4; ks++) {
            uint32_t bfr[4][2];
            const uint32_t* bp = bw + ks * 1024 + (lane & 3) * 128;
            #pragma unroll
            for (int f = 0; f < 4; f++) {
                bfr[f][0] = bp[wf[f]];
                bfr[f][1] = bp[512 + wf[f]];
            }
            const uint32_t colx = ((uint32_t)(ks * 32 + ab16)) ^ amask;
            uint32_t afr[4][4];
            #pragma unroll
            for (int mf = 0; mf < 4; mf++)
                ldsm4(afr[mf], sa + abase[mf] + colx);
            #pragma unroll
            for (int mf = 0; mf < 4; mf++)
                #pragma unroll
                for (int f = 0; f < 4; f++)
                    mma16(acc[mf][f], afr[mf], bfr[f]);
        }
    }
    __syncthreads();

    // ---------------- fused GLU epilogue (validated) ------------------------
    // acc: c0,c1 = (row=lane>>2, n=(lane&3)*2+{0,1}), c2,c3 = row+8.
    float* gs = smem;                 // [p2 = local_row*2 + b2][c], pitch 68
    const int pair = tid >> 2;
    const int h0 = (tid & 3) << 4;
    const int vLoc = pair >> 1, b2r = pair & 1;

    #pragma unroll 1
    for (int ch = 0; ch < 4; ch++) {
        if (wm == (ch >> 1)) {
            #pragma unroll
            for (int gg = 0; gg < 2; gg++) {
                const int g = (ch & 1) * 2 + gg;
                #pragma unroll
                for (int f = 0; f < 4; f++) {
                    const int n0 = wn * 32 + f * 8 + (lane & 3) * 2;
                    const int b2 = n0 >> 6, cc = n0 & 63;
                    const int lr = gg * 16 + (lane >> 2);
                    *(float2*)&gs[(lr * 2 + b2) * 68 + cc] =
                        make_float2(acc[g][f][0], acc[g][f][1]);
                    *(float2*)&gs[((lr + 8) * 2 + b2) * 68 + cc] =
                        make_float2(acc[g][f][2], acc[g][f][3]);
                }
            }
        }
        __syncthreads();

        const float* grow = &gs[pair * 68];
        const size_t orow = (size_t)((by << 7) + (ch << 5) + vLoc) * NBC
                          + (bx << 7) + (b2r << 6);
        #pragma unroll 4
        for (int hq = 0; hq < 4; hq++) {
            float v4[4];
            #pragma unroll
            for (int hs = 0; hs < 4; hs++) {
                const int h = h0 + hq * 4 + hs;
                float accL = __ldg(&bias[h]);
                float accR = __ldg(&bias[h + 64]);
                const float4* wl = (const float4*)(W + h * 64);
                const float4* wr = (const float4*)(W + (h + 64) * 64);
                #pragma unroll
                for (int c4 = 0; c4 < 16; c4++) {
                    float4 g = *(const float4*)(grow + c4 * 4);
                    float4 a = __ldg(wl + c4), r = __ldg(wr + c4);
                    accL += a.x * g.x + a.y * g.y + a.z * g.z + a.w * g.w;
                    accR += r.x * g.x + r.y * g.y + r.z * g.z + r.w * g.w;
                }
                v4[hs] = __fdividef(accL, 1.0f + __expf(-accR));
            }
            if (maxsrc) {
                float4 m = *(const float4*)(maxsrc + orow + h0 + hq * 4);
                v4[0] = fmaxf(v4[0], m.x); v4[1] = fmaxf(v4[1], m.y);
                v4[2] = fmaxf(v4[2], m.z); v4[3] = fmaxf(v4[3], m.w);
            }
            *(float4*)(out + orow + h0 + hq * 4) = make_float4(v4[0], v4[1], v4[2], v4[3]);
        }
        __syncthreads();
    }
}

extern "C" void kernel_launch(void* const* d_in, const int* in_sizes, int n_in,
                              void* d_out, int out_size)
{
    const float* x  = (const float*)d_in[0];
    const float* A  = (const float*)d_in[1];
    const float* W0 = (const float*)d_in[2];
    const float* b0 = (const float*)d_in[3];
    const float* W1 = (const float*)d_in[4];
    const float* b1 = (const float*)d_in[5];
    float* out = (float*)d_out;

    uint16_t* Ah = nullptr;
    uint32_t *Xh = nullptr, *H1h = nullptr;
    float* H1 = nullptr;
    cudaGetSymbolAddress((void**)&Ah, g_Ah);
    cudaGetSymbolAddress((void**)&Xh, g_Xh);
    cudaGetSymbolAddress((void**)&H1, g_H1);
    cudaGetSymbolAddress((void**)&H1h, g_H1h);
    if (!Ah || !Xh || !H1 || !H1h) return;

    cudaFuncSetAttribute(mma_glu_k, cudaFuncAttributeMaxDynamicSharedMemorySize, SMEMB);

    cvt_A_k<<<9216, 256>>>(A, Ah);                     // A -> tiled swizzled fp16
    cvt_packB_k<<<6144, 256>>>(x, Xh);                 // X -> tiled packed fp16
    mma_glu_k<<<dim3(32, 24), 256, SMEMB>>>(Ah, Xh, W0, b0, nullptr, H1);
    cvt_packB_k<<<6144, 256>>>(H1, H1h);               // H1 -> tiled packed fp16
    // kernel2 A band: rows 1024..2047 = bands 8..15 -> block offset 8*48 blocks
    mma_glu_k<<<dim3(32, 8), 256, SMEMB>>>(Ah + (size_t)8 * 48 * 8192,
                                           H1h, W1, b1,
                                           H1 + (size_t)NMID * NBC, out);
}

// round 16
// speedup vs baseline: 1.9769x; 1.0182x over previous
#include <cuda_runtime.h>
#include <cuda_fp16.h>
#include <cstdint>
#include <math.h>

#define KDIM 3072
#define NBC  4096
#define NMID 1024

#define STAGE_B 32768                 // A 16KB + B 16KB
#define NSTAGE  3
#define SMEMB   (128 + NSTAGE * STAGE_B)   // 98432 bytes

// ---- scratch: tile-contiguous, swizzled fp16 operands ----------------------
// A: [band 0..23][chunk 0..47] -> 16KB block = 128 rows x 128B (SW128-swizzled)
__device__ uint16_t g_Ah [(size_t)3072 * 3072];
// B: [bx 0..31][chunk 0..47] -> 16KB block = 32 k2-rows x 512B (word-XOR swizzled)
__device__ uint32_t g_Xh [(size_t)1536 * 4096];
__device__ float    g_H1 [(size_t)3072 * 4096];
__device__ uint32_t g_H1h[(size_t)1536 * 4096];

__device__ __forceinline__ uint32_t s2u(const void* p) {
    uint32_t a;
    asm("{\n.reg .u64 t;\ncvta.to.shared.u64 t,%1;\ncvt.u32.u64 %0,t;\n}" : "=r"(a) : "l"(p));
    return a;
}
__device__ __forceinline__ void ldsm4(uint32_t* r, uint32_t addr) {
    asm volatile("ldmatrix.sync.aligned.m8n8.x4.shared.b16 {%0,%1,%2,%3},[%4];"
                 : "=r"(r[0]), "=r"(r[1]), "=r"(r[2]), "=r"(r[3]) : "r"(addr));
}
__device__ __forceinline__ void mma16(float* d, const uint32_t* a, const uint32_t* b) {
    asm volatile("mma.sync.aligned.m16n8k16.row.col.f32.f16.f16.f32 "
                 "{%0,%1,%2,%3},{%4,%5,%6,%7},{%8,%9},{%0,%1,%2,%3};"
                 : "+f"(d[0]), "+f"(d[1]), "+f"(d[2]), "+f"(d[3])
                 : "r"(a[0]), "r"(a[1]), "r"(a[2]), "r"(a[3]), "r"(b[0]), "r"(b[1]));
}
__device__ __forceinline__ void mbar_wait(uint32_t mbar, uint32_t phase) {
    uint32_t d = 0;
    do {
        asm volatile("{\n.reg .pred p;\n"
            "mbarrier.try_wait.parity.acquire.cta.shared::cta.b64 p,[%1],%2,0x989680;\n"
            "selp.b32 %0,1,0,p;\n}" : "=r"(d) : "r"(mbar), "r"(phase) : "memory");
    } while (!d);
}

// ---------------- pre-pass: A -> fp16, tiled + SW128-swizzled ---------------
__global__ void cvt_A_k(const float* __restrict__ in, uint16_t* __restrict__ o)
{
    size_t i4 = (size_t)blockIdx.x * 256 + threadIdx.x;   // one float4 each
    float4 a = *((const float4*)in + i4);
    __half2 lo = __floats2half2_rn(a.x, a.y);
    __half2 hi = __floats2half2_rn(a.z, a.w);
    int row = (int)(i4 / 768);
    int c4  = (int)(i4 % 768) * 4;
    int band = row >> 7, r = row & 127, chunk = c4 >> 6, c = c4 & 63;
    size_t blk = (size_t)(band * 48 + chunk) * 16384;     // bytes
    uint32_t off = (uint32_t)(r * 128 + c * 2);
    uint32_t so = off ^ ((off >> 3) & 0x70);              // SW128
    *(uint2*)((char*)o + blk + so) = make_uint2(*reinterpret_cast<uint32_t*>(&lo),
                                                *reinterpret_cast<uint32_t*>(&hi));
}

// ---------------- pre-pass: B -> pair-packed fp16, tiled + swizzled ---------
// block (bx, chunk): 32 k2-rows x 128 words; word w stored at w ^ ((k2&3)<<3)
__global__ void cvt_packB_k(const float* __restrict__ in,   // (R, 4096)
                            uint32_t* __restrict__ o)
{
    size_t idx = (size_t)blockIdx.x * 256 + threadIdx.x;   // (k2, n-quad)
    int k2 = (int)(idx >> 10);
    int n4 = (int)(idx & 1023) << 2;
    float4 r0 = *(const float4*)(in + (size_t)(2 * k2) * NBC + n4);
    float4 r1 = *(const float4*)(in + (size_t)(2 * k2 + 1) * NBC + n4);
    __half2 w0 = __floats2half2_rn(r0.x, r1.x);   // .x low half
    __half2 w1 = __floats2half2_rn(r0.y, r1.y);
    __half2 w2 = __floats2half2_rn(r0.z, r1.z);
    __half2 w3 = __floats2half2_rn(r0.w, r1.w);
    uint4 v;
    v.x = *reinterpret_cast<uint32_t*>(&w0);
    v.y = *reinterpret_cast<uint32_t*>(&w1);
    v.z = *reinterpret_cast<uint32_t*>(&w2);
    v.w = *reinterpret_cast<uint32_t*>(&w3);
    int bx = n4 >> 7, w = n4 & 127, chunk = k2 >> 5, k2l = k2 & 31;
    uint32_t wp = (uint32_t)w ^ ((uint32_t)(k2l & 3) << 3);
    size_t dst = (size_t)(bx * 48 + chunk) * 4096 + k2l * 128 + wp;   // words
    *(uint4*)(o + dst) = v;
}

// ---------------------------------------------------------------------------
// D = Ag @ Bg via fp16 mma.sync, bulk-copy fed, producer/consumer mbarriers
// (NO per-iteration __syncthreads -> warps drift, tensor pipe stays fed).
// BM=BN=128, BK=64, 48 iters, 3-stage pipeline. Fused GLU(+max) epilogue.
// ---------------------------------------------------------------------------
__global__ __launch_bounds__(256, 2) void mma_glu_k(
    const uint16_t* __restrict__ Ablk, // band-tiled blocks, base of this band set
    const uint32_t* __restrict__ Bblk, // (bx,chunk)-tiled blocks
    const float* __restrict__ W, const float* __restrict__ bias,
    const float* __restrict__ maxsrc, float* __restrict__ out)
{
    extern __shared__ float smem[];
    char* smc = (char*)smem;
    const uint32_t smb = s2u(smem);
    const int tid = threadIdx.x, lane = tid & 31, wid = tid >> 5;
    const int bx = blockIdx.x, by = blockIdx.y;
    const int wm = wid >> 2, wn = wid & 3;   // warp grid 2(m) x 4(n)

    // full barriers: smb + 16*s ; empty barriers: smb + 48 + 16*s (count 8)
    if (tid == 0) {
        #pragma unroll
        for (int s = 0; s < NSTAGE; s++) {
            asm volatile("mbarrier.init.shared.b64 [%0], %1;"
                         :: "r"(smb + 16 * s), "r"(1) : "memory");
            asm volatile("mbarrier.init.shared.b64 [%0], %1;"
                         :: "r"(smb + 48 + 16 * s), "r"(8) : "memory");
        }
    }
    asm volatile("fence.proxy.async.shared::cta;" ::: "memory");
    __syncthreads();

    // A ldsm addressing: row = wm*64+mf*16+arow; swizzle mask = (lane&7)<<4
    const int arow = (lane & 7) + ((lane >> 3) & 1) * 8;
    const int ab16 = ((lane >> 4) & 1) * 16;
    const uint32_t amask = (uint32_t)(lane & 7) << 4;
    uint32_t abase[4];
    #pragma unroll
    for (int mf = 0; mf < 4; mf++)
        abase[mf] = (uint32_t)((wm * 64 + mf * 16 + arow) * 128);

    // B word offsets (within B region) pre-XORed per f
    const uint32_t bmask = (uint32_t)(lane & 3) << 3;
    uint32_t wf[4];
    #pragma unroll
    for (int f = 0; f < 4; f++)
        wf[f] = ((uint32_t)(wn * 32 + f * 8 + (lane >> 2))) ^ bmask;

    auto issue = [&](int i) {   // caller guarantees tid==0 and stage empty
        const int slot = i % NSTAGE;
        const uint32_t mbar = smb + 16 * slot;
        const uint32_t dst = smb + 128 + slot * STAGE_B;
        asm volatile("mbarrier.arrive.expect_tx.shared.b64 _, [%0], %1;"
                     :: "r"(mbar), "r"(2 * 16384) : "memory");
        const void* asrc = (const char*)Ablk + (size_t)(by * 48 + i) * 16384;
        const void* bsrc = (const char*)Bblk + (size_t)(bx * 48 + i) * 16384;
        asm volatile("cp.async.bulk.shared::cta.global.mbarrier::complete_tx::bytes "
                     "[%0], [%1], %2, [%3];"
                     :: "r"(dst), "l"(asrc), "r"(16384), "r"(mbar) : "memory");
        asm volatile("cp.async.bulk.shared::cta.global.mbarrier::complete_tx::bytes "
                     "[%0], [%1], %2, [%3];"
                     :: "r"(dst + 16384), "l"(bsrc), "r"(16384), "r"(mbar) : "memory");
    };

    float acc[4][4][4] = {};

    if (tid == 0) { issue(0); issue(1); issue(2); }

    for (int i = 0; i < 48; i++) {
        const int slot = i % NSTAGE;
        mbar_wait(smb + 16 * slot, (uint32_t)(i / 3) & 1);

        const uint32_t sa = smb + 128 + slot * STAGE_B;
        const uint32_t* bw = (const uint32_t*)(smc + 128 + slot * STAGE_B + 16384);
        #pragma unroll
        for (int ks = 0; ks < 4; ks++) {
            uint32_t bfr[4][2];
            const uint32_t* bp = bw + ks * 1024 + (lane & 3) * 128;
            #pragma unroll
            for (int f = 0; f < 4; f++) {
                bfr[f][0] = bp[wf[f]];
                bfr[f][1] = bp[512 + wf[f]];
            }
            const uint32_t colx = ((uint32_t)(ks * 32 + ab16)) ^ amask;
            uint32_t afr[4][4];
            #pragma unroll
            for (int mf = 0; mf < 4; mf++)
                ldsm4(afr[mf], sa + abase[mf] + colx);
            #pragma unroll
            for (int mf = 0; mf < 4; mf++)
                #pragma unroll
                for (int f = 0; f < 4; f++)
                    mma16(acc[mf][f], afr[mf], bfr[f]);
        }

        // this warp is done reading stage 'slot' for round i/3
        if (lane == 0)
            asm volatile("mbarrier.arrive.shared.b64 _, [%0];"
                         :: "r"(smb + 48 + 16 * slot) : "memory");
        // producer: refill this slot once ALL warps have consumed it
        if (tid == 0 && i + 3 < 48) {
            mbar_wait(smb + 48 + 16 * slot, (uint32_t)(i / 3) & 1);
            issue(i + 3);
        }
    }
    __syncthreads();

    // ---------------- fused GLU epilogue (validated) ------------------------
    // acc: c0,c1 = (row=lane>>2, n=(lane&3)*2+{0,1}), c2,c3 = row+8.
    float* gs = smem;                 // [p2 = local_row*2 + b2][c], pitch 68
    const int pair = tid >> 2;
    const int h0 = (tid & 3) << 4;
    const int vLoc = pair >> 1, b2r = pair & 1;

    #pragma unroll 1
    for (int ch = 0; ch < 4; ch++) {
        if (wm == (ch >> 1)) {
            #pragma unroll
            for (int gg = 0; gg < 2; gg++) {
                const int g = (ch & 1) * 2 + gg;
                #pragma unroll
                for (int f = 0; f < 4; f++) {
                    const int n0 = wn * 32 + f * 8 + (lane & 3) * 2;
                    const int b2 = n0 >> 6, cc = n0 & 63;
                    const int lr = gg * 16 + (lane >> 2);
                    *(float2*)&gs[(lr * 2 + b2) * 68 + cc] =
                        make_float2(acc[g][f][0], acc[g][f][1]);
                    *(float2*)&gs[((lr + 8) * 2 + b2) * 68 + cc] =
                        make_float2(acc[g][f][2], acc[g][f][3]);
                }
            }
        }
        __syncthreads();

        const float* grow = &gs[pair * 68];
        const size_t orow = (size_t)((by << 7) + (ch << 5) + vLoc) * NBC
                          + (bx << 7) + (b2r << 6);
        #pragma unroll 4
        for (int hq = 0; hq < 4; hq++) {
            float v4[4];
            #pragma unroll
            for (int hs = 0; hs < 4; hs++) {
                const int h = h0 + hq * 4 + hs;
                float accL = __ldg(&bias[h]);
                float accR = __ldg(&bias[h + 64]);
                const float4* wl = (const float4*)(W + h * 64);
                const float4* wr = (const float4*)(W + (h + 64) * 64);
                #pragma unroll
                for (int c4 = 0; c4 < 16; c4++) {
                    float4 g = *(const float4*)(grow + c4 * 4);
                    float4 a = __ldg(wl + c4), r = __ldg(wr + c4);
                    accL += a.x * g.x + a.y * g.y + a.z * g.z + a.w * g.w;
                    accR += r.x * g.x + r.y * g.y + r.z * g.z + r.w * g.w;
                }
                v4[hs] = __fdividef(accL, 1.0f + __expf(-accR));
            }
            if (maxsrc) {
                float4 m = *(const float4*)(maxsrc + orow + h0 + hq * 4);
                v4[0] = fmaxf(v4[0], m.x); v4[1] = fmaxf(v4[1], m.y);
                v4[2] = fmaxf(v4[2], m.z); v4[3] = fmaxf(v4[3], m.w);
            }
            *(float4*)(out + orow + h0 + hq * 4) = make_float4(v4[0], v4[1], v4[2], v4[3]);
        }
        __syncthreads();
    }
}

extern "C" void kernel_launch(void* const* d_in, const int* in_sizes, int n_in,
                              void* d_out, int out_size)
{
    const float* x  = (const float*)d_in[0];
    const float* A  = (const float*)d_in[1];
    const float* W0 = (const float*)d_in[2];
    const float* b0 = (const float*)d_in[3];
    const float* W1 = (const float*)d_in[4];
    const float* b1 = (const float*)d_in[5];
    float* out = (float*)d_out;

    uint16_t* Ah = nullptr;
    uint32_t *Xh = nullptr, *H1h = nullptr;
    float* H1 = nullptr;
    cudaGetSymbolAddress((void**)&Ah, g_Ah);
    cudaGetSymbolAddress((void**)&Xh, g_Xh);
    cudaGetSymbolAddress((void**)&H1, g_H1);
    cudaGetSymbolAddress((void**)&H1h, g_H1h);
    if (!Ah || !Xh || !H1 || !H1h) return;

    cudaFuncSetAttribute(mma_glu_k, cudaFuncAttributeMaxDynamicSharedMemorySize, SMEMB);

    cvt_A_k<<<9216, 256>>>(A, Ah);                     // A -> tiled swizzled fp16
    cvt_packB_k<<<6144, 256>>>(x, Xh);                 // X -> tiled packed fp16
    mma_glu_k<<<dim3(32, 24), 256, SMEMB>>>(Ah, Xh, W0, b0, nullptr, H1);
    cvt_packB_k<<<6144, 256>>>(H1, H1h);               // H1 -> tiled packed fp16
    // kernel2 A band: rows 1024..2047 = bands 8..15 -> block offset 8*48 blocks
    mma_glu_k<<<dim3(32, 8), 256, SMEMB>>>(Ah + (size_t)8 * 48 * 8192,
                                           H1h, W1, b1,
                                           H1 + (size_t)NMID * NBC, out);
}